// round 2
// baseline (speedup 1.0000x reference)
#include <cuda_runtime.h>
#include <math.h>

// Problem constants
#define BATCH 8
#define MCH   63          // raw basis channels
#define MH    64          // with ones channel prepended
#define HW    307200      // 480*640
#define NBLK  40          // stats blocks per batch
#define CHUNK 7680        // HW / NBLK
#define SUB   2560        // sub-chunk size for compaction
#define NSUB  3           // CHUNK / SUB
#define PPT   10          // pixels per thread per sub-chunk (256*10 = 2560)
#define NV    16          // valid pixels per accumulation group

// Scratch (device globals; no allocation allowed)
__device__ float g_partA[BATCH * NBLK * 4096];   // per-block partial XtX
__device__ float g_partX[BATCH * NBLK * 64];     // per-block partial Xty
__device__ float g_partS[BATCH * NBLK * 2];      // per-block yty, n
__device__ float g_fit[BATCH * (4096 + 64)];     // per-batch G (=L^-1/sqrt(beta), full w/ zeros) then w

// ---------------------------------------------------------------------------
// Kernel 1: sparse masked Gram accumulation.
// Each block handles CHUNK pixels of one batch. Valid pixels are compacted
// deterministically (block-wide scan), then processed in groups of NV with a
// 16x16 thread tiling of the 64x64 outer-product accumulator.
// ---------------------------------------------------------------------------
__global__ void __launch_bounds__(256) stats_kernel(const float* __restrict__ bases,
                                                    const float* __restrict__ targets)
{
    const int b   = blockIdx.x / NBLK;
    const int blk = blockIdx.x % NBLK;
    const float* tgb = targets + (size_t)b * HW;
    const float* bs  = bases   + (size_t)b * MCH * HW;

    __shared__ int   pix [SUB];
    __shared__ float yls [SUB];
    __shared__ float bv  [NV][64];
    __shared__ float yg  [NV];
    __shared__ int   scan[256];

    const int tid = threadIdx.x;
    const int ti  = tid >> 4;      // row tile 0..15
    const int tj  = tid & 15;      // col tile 0..15

    float acc[4][4];
#pragma unroll
    for (int i = 0; i < 4; i++)
#pragma unroll
        for (int j = 0; j < 4; j++) acc[i][j] = 0.f;

    float xty = 0.f, yty = 0.f, ncnt = 0.f;

    for (int s = 0; s < NSUB; s++) {
        const int base = blk * CHUNK + s * SUB;
        const int p0   = base + tid * PPT;

        // count pass
        int cnt = 0;
#pragma unroll
        for (int k = 0; k < PPT; k++) {
            float y = tgb[p0 + k];
            if (isfinite(y)) cnt++;
        }
        scan[tid] = cnt;
        __syncthreads();
        // inclusive scan (Hillis-Steele)
        for (int off = 1; off < 256; off <<= 1) {
            int v = (tid >= off) ? scan[tid - off] : 0;
            __syncthreads();
            scan[tid] += v;
            __syncthreads();
        }
        int wo    = scan[tid] - cnt;   // exclusive offset
        int total = scan[255];
        __syncthreads();

        // write pass (deterministic order)
#pragma unroll
        for (int k = 0; k < PPT; k++) {
            float y = tgb[p0 + k];
            if (isfinite(y)) { pix[wo] = p0 + k; yls[wo] = y; wo++; }
        }
        __syncthreads();

        if (tid == 0) ncnt += (float)total;

        const int ng = (total + NV - 1) / NV;
        for (int g = 0; g < ng; g++) {
            const int base_v = g * NV;
            // stage NV basis vectors (64 channels each, channel 0 = ones)
#pragma unroll
            for (int r = 0; r < 4; r++) {
                int idx = r * 256 + tid;
                int v = idx >> 6, c = idx & 63;
                int gv = base_v + v;
                float val = 0.f;
                if (gv < total)
                    val = (c == 0) ? 1.f : bs[(size_t)(c - 1) * HW + pix[gv]];
                bv[v][c] = val;
            }
            if (tid < NV) {
                int gv = base_v + tid;
                yg[tid] = (gv < total) ? yls[gv] : 0.f;
            }
            __syncthreads();

            const float4* bv4 = (const float4*)bv;  // bv4[v*16 + q]
#pragma unroll
            for (int v = 0; v < NV; v++) {
                float4 R = bv4[v * 16 + ti];
                float4 C = bv4[v * 16 + tj];
                acc[0][0] += R.x * C.x; acc[0][1] += R.x * C.y; acc[0][2] += R.x * C.z; acc[0][3] += R.x * C.w;
                acc[1][0] += R.y * C.x; acc[1][1] += R.y * C.y; acc[1][2] += R.y * C.z; acc[1][3] += R.y * C.w;
                acc[2][0] += R.z * C.x; acc[2][1] += R.z * C.y; acc[2][2] += R.z * C.z; acc[2][3] += R.z * C.w;
                acc[3][0] += R.w * C.x; acc[3][1] += R.w * C.y; acc[3][2] += R.w * C.z; acc[3][3] += R.w * C.w;
            }
            if (tid < 64) {
#pragma unroll
                for (int v = 0; v < NV; v++) xty += bv[v][tid] * yg[v];
            }
            if (tid == 64) {
#pragma unroll
                for (int v = 0; v < NV; v++) yty += yg[v] * yg[v];
            }
            __syncthreads();
        }
        __syncthreads();   // before reusing pix/yls/scan
    }

    // write partials (deterministic positions)
    float* pa = g_partA + ((size_t)b * NBLK + blk) * 4096;
#pragma unroll
    for (int i = 0; i < 4; i++)
#pragma unroll
        for (int j = 0; j < 4; j++)
            pa[(ti * 4 + i) * 64 + (tj * 4 + j)] = acc[i][j];
    if (tid < 64)  g_partX[((size_t)b * NBLK + blk) * 64 + tid] = xty;
    if (tid == 64) g_partS[((size_t)b * NBLK + blk) * 2 + 0] = yty;
    if (tid == 0)  g_partS[((size_t)b * NBLK + blk) * 2 + 1] = ncnt;
}

// ---------------------------------------------------------------------------
// Kernel 2: per-batch reduce + Cholesky + solves + beta recurrence + L^-1.
// One block per batch, 256 threads (rows 0..63 active for the linear algebra).
// ---------------------------------------------------------------------------
__global__ void __launch_bounds__(256) solve_kernel(float* __restrict__ out)
{
    const int b   = blockIdx.x;
    const int tid = threadIdx.x;

    __shared__ float A [64 * 65];
    __shared__ float Li[64 * 65];
    __shared__ float xty[64], wv[64], zv[64];
    __shared__ float sc[4];   // 0:yty 1:n 2:beta

    // reduce partials
    for (int e = tid; e < 4096; e += 256) {
        float s = 0.f;
#pragma unroll 4
        for (int k = 0; k < NBLK; k++) s += g_partA[((size_t)b * NBLK + k) * 4096 + e];
        A[(e >> 6) * 65 + (e & 63)] = s;
    }
    if (tid < 64) {
        float s = 0.f;
#pragma unroll 4
        for (int k = 0; k < NBLK; k++) s += g_partX[((size_t)b * NBLK + k) * 64 + tid];
        xty[tid] = s;
    }
    if (tid == 0) {
        float yt = 0.f, n = 0.f;
        for (int k = 0; k < NBLK; k++) {
            yt += g_partS[((size_t)b * NBLK + k) * 2 + 0];
            n  += g_partS[((size_t)b * NBLK + k) * 2 + 1];
        }
        sc[0] = yt; sc[1] = n;
    }
    __syncthreads();

    // Cholesky (in-place, lower)
    for (int k = 0; k < 64; k++) {
        if (tid == 0) A[k * 65 + k] = sqrtf(A[k * 65 + k]);
        __syncthreads();
        if (tid > k && tid < 64) A[tid * 65 + k] /= A[k * 65 + k];
        __syncthreads();
        if (tid > k && tid < 64) {
            float l = A[tid * 65 + k];
            for (int i = k + 1; i <= tid; i++) A[tid * 65 + i] -= l * A[i * 65 + k];
        }
        __syncthreads();
    }

    // forward: L z = xty
    if (tid < 64) zv[tid] = xty[tid];
    __syncthreads();
    for (int k = 0; k < 64; k++) {
        if (tid == k) zv[k] /= A[k * 65 + k];
        __syncthreads();
        if (tid > k && tid < 64) zv[tid] -= A[tid * 65 + k] * zv[k];
        __syncthreads();
    }
    // backward: L^T w = z
    if (tid < 64) wv[tid] = zv[tid];
    __syncthreads();
    for (int k = 63; k >= 0; k--) {
        if (tid == k) wv[k] /= A[k * 65 + k];
        __syncthreads();
        if (tid < k) wv[tid] -= A[k * 65 + tid] * wv[k];
        __syncthreads();
    }

    // E_d and beta recurrence (matches reference semantics exactly)
    if (tid == 0) {
        float yt = sc[0], n = sc[1];
        float wx = 0.f, zz = 0.f;
        for (int c = 0; c < 64; c++) { wx += wv[c] * xty[c]; zz += zv[c] * zv[c]; }
        float E = yt - 2.f * wx + zz;   // residual sum of squares on valid pixels
        float beta0 = sqrtf(n), beta = beta0;
        bool done = false;
        for (int it = 0; it < 5; it++) {
            float bn   = n / (E + 64.f / beta);
            bool  conv = fabsf(bn / beta0 - 1.f) < 0.02f;
            if (!done) { beta = bn; beta0 = bn; }
            done = done || conv;
        }
        sc[2] = beta;
    }
    __syncthreads();

    // L^{-1}: thread c computes column c independently (no cross-thread deps)
    if (tid < 64) {
        const int c = tid;
        for (int k = c; k < 64; k++) {
            float s = (k == c) ? 1.f : 0.f;
            for (int j = c; j < k; j++) s -= A[k * 65 + j] * Li[j * 65 + c];
            Li[k * 65 + c] = s / A[k * 65 + k];
        }
    }
    __syncthreads();

    const float sb = rsqrtf(sc[2]);   // G = L^{-1} / sqrt(beta)
    float* G = g_fit + (size_t)b * (4096 + 64);
    for (int e = tid; e < 4096; e += 256) {
        int i = e >> 6, j = e & 63;
        G[e] = (j <= i) ? Li[i * 65 + j] * sb : 0.f;
    }
    if (tid < 64) {
        G[4096 + tid] = wv[tid];
        // weights output: after logits block
        out[(size_t)BATCH * HW + (size_t)b * 64 + tid] = wv[tid];
    }
}

// ---------------------------------------------------------------------------
// Kernel 3: per-pixel prediction + variance.
// pred = w . b ;  var = || G b ||^2  (G lower-triangular, zeros above).
// Fully unrolled triangular matvec, float4 broadcast loads of G from smem.
// ---------------------------------------------------------------------------
#define CPT 4   // pixels per thread
__global__ void __launch_bounds__(256) pred_kernel(const float* __restrict__ bases,
                                                   float* __restrict__ out)
{
    const int blocks_per_batch = HW / (256 * CPT);   // 300
    const int b   = blockIdx.x / blocks_per_batch;
    const int blk = blockIdx.x % blocks_per_batch;

    __shared__ float4 G4[64 * 16];
    __shared__ float  ws[64];

    const float* fit = g_fit + (size_t)b * (4096 + 64);
    for (int e = threadIdx.x; e < 1024; e += 256) G4[e] = ((const float4*)fit)[e];
    if (threadIdx.x < 64) ws[threadIdx.x] = fit[4096 + threadIdx.x];
    __syncthreads();

    const float* bs   = bases + (size_t)b * MCH * HW;
    float* outL = out + (size_t)b * HW;
    float* outV = out + (size_t)BATCH * HW + (size_t)BATCH * 64 + (size_t)b * HW;

    const int p0 = blk * (256 * CPT) + threadIdx.x;

#pragma unroll 1
    for (int q = 0; q < CPT; q++) {
        const int p = p0 + q * 256;

        float bvv[64];
        bvv[0] = 1.f;
#pragma unroll
        for (int c = 1; c < 64; c++) bvv[c] = bs[(size_t)(c - 1) * HW + p];

        float pred = 0.f;
#pragma unroll
        for (int c = 0; c < 64; c++) pred += ws[c] * bvv[c];

        float var = 0.f;
#pragma unroll
        for (int i = 0; i < 64; i++) {
            float t = 0.f;
#pragma unroll
            for (int j4 = 0; j4 <= i / 4; j4++) {   // upper-tri entries are 0
                float4 g = G4[i * 16 + j4];
                t += g.x * bvv[4 * j4] + g.y * bvv[4 * j4 + 1]
                   + g.z * bvv[4 * j4 + 2] + g.w * bvv[4 * j4 + 3];
            }
            var += t * t;
        }
        outL[p] = pred;
        outV[p] = var;
    }
}

// ---------------------------------------------------------------------------
extern "C" void kernel_launch(void* const* d_in, const int* in_sizes, int n_in,
                              void* d_out, int out_size)
{
    const float* bases   = (const float*)d_in[0];
    const float* targets = (const float*)d_in[1];
    // robustness: identify by size (bases = 8*63*307200, targets = 8*307200)
    if (n_in >= 2 && in_sizes[0] < in_sizes[1]) {
        const float* t = bases; bases = targets; targets = t;
    }
    float* out = (float*)d_out;

    stats_kernel<<<BATCH * NBLK, 256>>>(bases, targets);
    solve_kernel<<<BATCH, 256>>>(out);
    pred_kernel<<<BATCH * (HW / (256 * CPT)), 256>>>(bases, out);
}

// round 4
// speedup vs baseline: 4.0121x; 4.0121x over previous
#include <cuda_runtime.h>
#include <math.h>

// Problem constants
#define BATCH 8
#define MCH   63          // raw basis channels
#define MH    64          // with ones channel prepended
#define HW    307200      // 480*640
#define NBLK  40          // stats blocks per batch
#define CHUNK 7680        // HW / NBLK
#define SUB   2560        // sub-chunk size for compaction
#define NSUB  3           // CHUNK / SUB
#define PPT   10          // pixels per thread per sub-chunk (256*10 = 2560)
#define NV    16          // valid pixels per accumulation group

// Scratch (device globals; no allocation allowed)
__device__ float g_partA[BATCH * NBLK * 4096];   // per-block partial XtX
__device__ float g_partX[BATCH * NBLK * 64];     // per-block partial Xty
__device__ float g_partS[BATCH * NBLK * 2];      // per-block yty, n
__device__ float g_fit[BATCH * (4096 + 64)];     // per-batch G (=L^-1/sqrt(beta)) then w

// ---------------------------------------------------------------------------
// Kernel 1: sparse masked Gram accumulation (unchanged from passing version).
// ---------------------------------------------------------------------------
__global__ void __launch_bounds__(256) stats_kernel(const float* __restrict__ bases,
                                                    const float* __restrict__ targets)
{
    const int b   = blockIdx.x / NBLK;
    const int blk = blockIdx.x % NBLK;
    const float* tgb = targets + (size_t)b * HW;
    const float* bs  = bases   + (size_t)b * MCH * HW;

    __shared__ int   pix [SUB];
    __shared__ float yls [SUB];
    __shared__ float bv  [NV][64];
    __shared__ float yg  [NV];
    __shared__ int   scan[256];

    const int tid = threadIdx.x;
    const int ti  = tid >> 4;
    const int tj  = tid & 15;

    float acc[4][4];
#pragma unroll
    for (int i = 0; i < 4; i++)
#pragma unroll
        for (int j = 0; j < 4; j++) acc[i][j] = 0.f;

    float xty = 0.f, yty = 0.f, ncnt = 0.f;

    for (int s = 0; s < NSUB; s++) {
        const int base = blk * CHUNK + s * SUB;
        const int p0   = base + tid * PPT;

        int cnt = 0;
#pragma unroll
        for (int k = 0; k < PPT; k++) {
            float y = tgb[p0 + k];
            if (isfinite(y)) cnt++;
        }
        scan[tid] = cnt;
        __syncthreads();
        for (int off = 1; off < 256; off <<= 1) {
            int v = (tid >= off) ? scan[tid - off] : 0;
            __syncthreads();
            scan[tid] += v;
            __syncthreads();
        }
        int wo    = scan[tid] - cnt;
        int total = scan[255];
        __syncthreads();

#pragma unroll
        for (int k = 0; k < PPT; k++) {
            float y = tgb[p0 + k];
            if (isfinite(y)) { pix[wo] = p0 + k; yls[wo] = y; wo++; }
        }
        __syncthreads();

        if (tid == 0) ncnt += (float)total;

        const int ng = (total + NV - 1) / NV;
        for (int g = 0; g < ng; g++) {
            const int base_v = g * NV;
#pragma unroll
            for (int r = 0; r < 4; r++) {
                int idx = r * 256 + tid;
                int v = idx >> 6, c = idx & 63;
                int gv = base_v + v;
                float val = 0.f;
                if (gv < total)
                    val = (c == 0) ? 1.f : bs[(size_t)(c - 1) * HW + pix[gv]];
                bv[v][c] = val;
            }
            if (tid < NV) {
                int gv = base_v + tid;
                yg[tid] = (gv < total) ? yls[gv] : 0.f;
            }
            __syncthreads();

            const float4* bv4 = (const float4*)bv;
#pragma unroll
            for (int v = 0; v < NV; v++) {
                float4 R = bv4[v * 16 + ti];
                float4 C = bv4[v * 16 + tj];
                acc[0][0] += R.x * C.x; acc[0][1] += R.x * C.y; acc[0][2] += R.x * C.z; acc[0][3] += R.x * C.w;
                acc[1][0] += R.y * C.x; acc[1][1] += R.y * C.y; acc[1][2] += R.y * C.z; acc[1][3] += R.y * C.w;
                acc[2][0] += R.z * C.x; acc[2][1] += R.z * C.y; acc[2][2] += R.z * C.z; acc[2][3] += R.z * C.w;
                acc[3][0] += R.w * C.x; acc[3][1] += R.w * C.y; acc[3][2] += R.w * C.z; acc[3][3] += R.w * C.w;
            }
            if (tid < 64) {
#pragma unroll
                for (int v = 0; v < NV; v++) xty += bv[v][tid] * yg[v];
            }
            if (tid == 64) {
#pragma unroll
                for (int v = 0; v < NV; v++) yty += yg[v] * yg[v];
            }
            __syncthreads();
        }
        __syncthreads();
    }

    float* pa = g_partA + ((size_t)b * NBLK + blk) * 4096;
#pragma unroll
    for (int i = 0; i < 4; i++)
#pragma unroll
        for (int j = 0; j < 4; j++)
            pa[(ti * 4 + i) * 64 + (tj * 4 + j)] = acc[i][j];
    if (tid < 64)  g_partX[((size_t)b * NBLK + blk) * 64 + tid] = xty;
    if (tid == 64) g_partS[((size_t)b * NBLK + blk) * 2 + 0] = yty;
    if (tid == 0)  g_partS[((size_t)b * NBLK + blk) * 2 + 1] = ncnt;
}

// ---------------------------------------------------------------------------
// Kernel 2: per-batch reduce + Cholesky + solves + beta recurrence + L^-1.
// ---------------------------------------------------------------------------
__global__ void __launch_bounds__(256) solve_kernel(float* __restrict__ out)
{
    const int b   = blockIdx.x;
    const int tid = threadIdx.x;

    __shared__ float A [64 * 65];
    __shared__ float Li[64 * 65];
    __shared__ float xty[64], wv[64], zv[64];
    __shared__ float sc[4];

    for (int e = tid; e < 4096; e += 256) {
        float s = 0.f;
#pragma unroll 4
        for (int k = 0; k < NBLK; k++) s += g_partA[((size_t)b * NBLK + k) * 4096 + e];
        A[(e >> 6) * 65 + (e & 63)] = s;
    }
    if (tid < 64) {
        float s = 0.f;
#pragma unroll 4
        for (int k = 0; k < NBLK; k++) s += g_partX[((size_t)b * NBLK + k) * 64 + tid];
        xty[tid] = s;
    }
    if (tid == 0) {
        float yt = 0.f, n = 0.f;
        for (int k = 0; k < NBLK; k++) {
            yt += g_partS[((size_t)b * NBLK + k) * 2 + 0];
            n  += g_partS[((size_t)b * NBLK + k) * 2 + 1];
        }
        sc[0] = yt; sc[1] = n;
    }
    __syncthreads();

    for (int k = 0; k < 64; k++) {
        if (tid == 0) A[k * 65 + k] = sqrtf(A[k * 65 + k]);
        __syncthreads();
        if (tid > k && tid < 64) A[tid * 65 + k] /= A[k * 65 + k];
        __syncthreads();
        if (tid > k && tid < 64) {
            float l = A[tid * 65 + k];
            for (int i = k + 1; i <= tid; i++) A[tid * 65 + i] -= l * A[i * 65 + k];
        }
        __syncthreads();
    }

    if (tid < 64) zv[tid] = xty[tid];
    __syncthreads();
    for (int k = 0; k < 64; k++) {
        if (tid == k) zv[k] /= A[k * 65 + k];
        __syncthreads();
        if (tid > k && tid < 64) zv[tid] -= A[tid * 65 + k] * zv[k];
        __syncthreads();
    }
    if (tid < 64) wv[tid] = zv[tid];
    __syncthreads();
    for (int k = 63; k >= 0; k--) {
        if (tid == k) wv[k] /= A[k * 65 + k];
        __syncthreads();
        if (tid < k) wv[tid] -= A[k * 65 + tid] * wv[k];
        __syncthreads();
    }

    if (tid == 0) {
        float yt = sc[0], n = sc[1];
        float wx = 0.f, zz = 0.f;
        for (int c = 0; c < 64; c++) { wx += wv[c] * xty[c]; zz += zv[c] * zv[c]; }
        float E = yt - 2.f * wx + zz;
        float beta0 = sqrtf(n), beta = beta0;
        bool done = false;
        for (int it = 0; it < 5; it++) {
            float bn   = n / (E + 64.f / beta);
            bool  conv = fabsf(bn / beta0 - 1.f) < 0.02f;
            if (!done) { beta = bn; beta0 = bn; }
            done = done || conv;
        }
        sc[2] = beta;
    }
    __syncthreads();

    if (tid < 64) {
        const int c = tid;
        for (int k = c; k < 64; k++) {
            float s = (k == c) ? 1.f : 0.f;
            for (int j = c; j < k; j++) s -= A[k * 65 + j] * Li[j * 65 + c];
            Li[k * 65 + c] = s / A[k * 65 + k];
        }
    }
    __syncthreads();

    const float sb = rsqrtf(sc[2]);
    float* G = g_fit + (size_t)b * (4096 + 64);
    for (int e = tid; e < 4096; e += 256) {
        int i = e >> 6, j = e & 63;
        G[e] = (j <= i) ? Li[i * 65 + j] * sb : 0.f;
    }
    if (tid < 64) {
        G[4096 + tid] = wv[tid];
        out[(size_t)BATCH * HW + (size_t)b * 64 + tid] = wv[tid];
    }
}

// ---------------------------------------------------------------------------
// Kernel 3: per-pixel prediction + variance.
// pred = w . b ;  var = || G b ||^2  (G lower-triangular, zeros above diag).
// Rows generated with literal-index macros so every bv[] index is a
// compile-time constant -> bv stays in registers (no local-memory demotion).
// ---------------------------------------------------------------------------
#define ROW(I) do {                                                         \
    float t = 0.f;                                                          \
    _Pragma("unroll")                                                       \
    for (int j4 = 0; j4 <= ((I) >> 2); ++j4) {                              \
        float4 g = Gs[(I) * 16 + j4];                                       \
        t = fmaf(g.x, bv[4 * j4 + 0], t);                                   \
        t = fmaf(g.y, bv[4 * j4 + 1], t);                                   \
        t = fmaf(g.z, bv[4 * j4 + 2], t);                                   \
        t = fmaf(g.w, bv[4 * j4 + 3], t);                                   \
    }                                                                       \
    var = fmaf(t, t, var);                                                  \
} while (0)

#define ROW4(I) ROW(I); ROW((I) + 1); ROW((I) + 2); ROW((I) + 3)

__global__ void __launch_bounds__(256, 2) pred_kernel(const float* __restrict__ bases,
                                                      float* __restrict__ out)
{
    const int blocks_per_batch = HW / 256;   // 1200
    const int b   = blockIdx.x / blocks_per_batch;
    const int blk = blockIdx.x % blocks_per_batch;

    __shared__ float4 Gs[64 * 16];   // 16 KB: G rows as float4
    __shared__ float  ws[64];

    const float* fit = g_fit + (size_t)b * (4096 + 64);
    {
        const float4* fit4 = (const float4*)fit;
#pragma unroll
        for (int r = 0; r < 4; r++) Gs[r * 256 + threadIdx.x] = fit4[r * 256 + threadIdx.x];
        if (threadIdx.x < 64) ws[threadIdx.x] = fit[4096 + threadIdx.x];
    }
    __syncthreads();

    const float* bs = bases + (size_t)b * MCH * HW;
    const int p = blk * 256 + threadIdx.x;

    // basis vector in registers (constant indices only)
    float bv[64];
    bv[0] = 1.f;
#pragma unroll
    for (int c = 1; c < 64; c++) bv[c] = __ldg(bs + (size_t)(c - 1) * HW + p);

    // prediction
    float pred = 0.f;
#pragma unroll
    for (int c = 0; c < 64; c++) pred = fmaf(ws[c], bv[c], pred);

    // variance: || G b ||^2, triangular rows fully unrolled
    float var = 0.f;
    ROW4(0);  ROW4(4);  ROW4(8);  ROW4(12);
    ROW4(16); ROW4(20); ROW4(24); ROW4(28);
    ROW4(32); ROW4(36); ROW4(40); ROW4(44);
    ROW4(48); ROW4(52); ROW4(56); ROW4(60);

    out[(size_t)b * HW + p] = pred;
    out[(size_t)BATCH * HW + (size_t)BATCH * 64 + (size_t)b * HW + p] = var;
}

// ---------------------------------------------------------------------------
extern "C" void kernel_launch(void* const* d_in, const int* in_sizes, int n_in,
                              void* d_out, int out_size)
{
    const float* bases   = (const float*)d_in[0];
    const float* targets = (const float*)d_in[1];
    if (n_in >= 2 && in_sizes[0] < in_sizes[1]) {
        const float* t = bases; bases = targets; targets = t;
    }
    float* out = (float*)d_out;

    stats_kernel<<<BATCH * NBLK, 256>>>(bases, targets);
    solve_kernel<<<BATCH, 256>>>(out);
    pred_kernel<<<BATCH * (HW / 256), 256>>>(bases, out);
}